// round 10
// baseline (speedup 1.0000x reference)
#include <cuda_runtime.h>
#include <cuda_fp16.h>
#include <cstdint>

// ============================================================================
// Problem constants
// ============================================================================
#define IN_F   2048
#define HID_F  8192
#define OUT_F  2048
#define BATCH  4096

// ============================================================================
// Scratch (device globals — allocation-free rule workaround)
// ============================================================================
__device__ __align__(16) __half g_X [(size_t)BATCH * IN_F];    // x  -> fp16
__device__ __align__(16) __half g_W1[(size_t)IN_F  * HID_F];   // W1 -> fp16 (same [K,N] layout)
__device__ __align__(16) __half g_W2[(size_t)HID_F * OUT_F];   // W2 -> fp16
__device__ __align__(16) __half g_H [(size_t)BATCH * HID_F];   // relu(x@W1+b1) fp16

// ============================================================================
// Helpers (sm_80-baseline PTX only — legal under compute_103 target)
// ============================================================================
__device__ __forceinline__ uint32_t smem_to_u32(const void* smem_ptr) {
    uint32_t addr;
    asm("{ .reg .u64 tmp; cvta.to.shared.u64 tmp, %1; cvt.u32.u64 %0, tmp; }"
        : "=r"(addr) : "l"(smem_ptr));
    return addr;
}

__device__ __forceinline__ void cp_async16(uint32_t dst, const void* src) {
    asm volatile("cp.async.cg.shared.global [%0], [%1], 16;" :: "r"(dst), "l"(src));
}
__device__ __forceinline__ void cp_commit() {
    asm volatile("cp.async.commit_group;" ::: "memory");
}

__device__ __forceinline__ void ldm_x4(uint32_t* r, uint32_t addr) {
    asm volatile("ldmatrix.sync.aligned.m8n8.x4.shared.b16 {%0,%1,%2,%3}, [%4];"
                 : "=r"(r[0]), "=r"(r[1]), "=r"(r[2]), "=r"(r[3]) : "r"(addr));
}
__device__ __forceinline__ void ldm_x4_trans(uint32_t* r, uint32_t addr) {
    asm volatile("ldmatrix.sync.aligned.m8n8.x4.trans.shared.b16 {%0,%1,%2,%3}, [%4];"
                 : "=r"(r[0]), "=r"(r[1]), "=r"(r[2]), "=r"(r[3]) : "r"(addr));
}

__device__ __forceinline__ void mma16816(float* d, const uint32_t* a, const uint32_t* b) {
    asm volatile(
        "mma.sync.aligned.m16n8k16.row.col.f32.f16.f16.f32 "
        "{%0,%1,%2,%3}, {%4,%5,%6,%7}, {%8,%9}, {%0,%1,%2,%3};"
        : "+f"(d[0]), "+f"(d[1]), "+f"(d[2]), "+f"(d[3])
        : "r"(a[0]), "r"(a[1]), "r"(a[2]), "r"(a[3]), "r"(b[0]), "r"(b[1]));
}

// ============================================================================
// fp32 -> fp16 conversion (4 elems / thread)
// ============================================================================
template<int SEL>
__global__ void __launch_bounds__(256) f2h_kernel(const float* __restrict__ src) {
    __half* dst = (SEL == 0) ? g_X : (SEL == 1) ? g_W1 : g_W2;
    size_t i = (size_t)blockIdx.x * blockDim.x + threadIdx.x;
    float4 v = reinterpret_cast<const float4*>(src)[i];
    __half2 h0 = __floats2half2_rn(v.x, v.y);
    __half2 h1 = __floats2half2_rn(v.z, v.w);
    reinterpret_cast<__half2*>(dst)[2 * i]     = h0;
    reinterpret_cast<__half2*>(dst)[2 * i + 1] = h1;
}

// ============================================================================
// fp16 GEMM, fp32 accumulate:  C[M,N] = A[M,K] @ B[K,N]  (+bias, activation)
//   EPI==0: A=g_X,  B=g_W1, relu    -> g_H (fp16)      [M=4096,K=2048,N=8192]
//   EPI==1: A=g_H,  B=g_W2, sigmoid -> outF (fp32)     [M=4096,K=8192,N=2048]
//
// CTA tile 128x128, BK=32, 4-stage cp.async pipeline, 256 threads (8 warps
// arranged 4(m) x 2(n), warp tile 32x64). Padded smem rows:
//   A stage: [128][40] fp16 (row 80B)   — ldmatrix conflict-free
//   B stage: [32][136] fp16 (row 272B)  — ldmatrix.trans conflict-free
// ============================================================================
template<int EPI>
__global__ void __launch_bounds__(256)
hgemm_kernel(const float* __restrict__ bias, float* __restrict__ outF)
{
    constexpr int K  = (EPI == 0) ? IN_F  : HID_F;
    constexpr int N  = (EPI == 0) ? HID_F : OUT_F;
    constexpr int BM = 128, BN = 128, BK = 32, S = 4;
    constexpr int KT = K / BK;
    constexpr int A_STG = BM * 40 * 2;    // 10240 B
    constexpr int B_STG = BK * 136 * 2;   //  8704 B

    const __half* A = (EPI == 0) ? g_X  : g_H;
    const __half* B = (EPI == 0) ? g_W1 : g_W2;

    extern __shared__ char smem[];
    const uint32_t sA = smem_to_u32(smem);
    const uint32_t sB = sA + S * A_STG;

    const int tid  = threadIdx.x;
    const int lane = tid & 31;
    const int wid  = tid >> 5;
    const int wm   = (wid & 3) << 5;       // warp m offset: 0,32,64,96
    const int wn   = (wid >> 2) << 6;      // warp n offset: 0,64
    const int m0   = blockIdx.x * BM;
    const int n0   = blockIdx.y * BN;

    auto load_stage = [&](int kt, int s) {
        const int k0 = kt * BK;
        const uint32_t as = sA + s * A_STG;
        // A tile: 128 rows x 32 halves = 512 x 16B chunks (4 chunks/row)
#pragma unroll
        for (int it = 0; it < 2; ++it) {
            int g = tid + it * 256;
            int r = g >> 2, c = g & 3;
            cp_async16(as + r * 80 + c * 16,
                       A + (size_t)(m0 + r) * K + k0 + c * 8);
        }
        const uint32_t bs = sB + s * B_STG;
        // B tile: 32 rows x 128 halves = 512 x 16B chunks (16 chunks/row)
#pragma unroll
        for (int it = 0; it < 2; ++it) {
            int g = tid + it * 256;
            int r = g >> 4, c = g & 15;
            cp_async16(bs + r * 272 + c * 16,
                       B + (size_t)(k0 + r) * N + n0 + c * 8);
        }
        cp_commit();
    };

    float acc[2][8][4];
#pragma unroll
    for (int mt = 0; mt < 2; ++mt)
#pragma unroll
        for (int nt = 0; nt < 8; ++nt)
#pragma unroll
            for (int q = 0; q < 4; ++q) acc[mt][nt][q] = 0.0f;

    // prologue: fill S-1 stages
#pragma unroll
    for (int st = 0; st < S - 1; ++st) load_stage(st, st);

    const int arow = lane & 15;            // ldmatrix row-within-16
    const int acol = (lane >> 4) << 3;     // 0 or 8 (col half)

    for (int kt = 0; kt < KT; ++kt) {
        if (kt < KT - (S - 1)) asm volatile("cp.async.wait_group %0;" :: "n"(S - 2) : "memory");
        else                   asm volatile("cp.async.wait_group 0;" ::: "memory");
        __syncthreads();

        if (kt + S - 1 < KT) load_stage(kt + S - 1, (kt + S - 1) % S);

        const uint32_t as = sA + (kt % S) * A_STG;
        const uint32_t bs = sB + (kt % S) * B_STG;
#pragma unroll
        for (int ks = 0; ks < 2; ++ks) {
            uint32_t af[2][4];
#pragma unroll
            for (int mt = 0; mt < 2; ++mt)
                ldm_x4(af[mt], as + (wm + mt * 16 + arow) * 80 + (ks * 16 + acol) * 2);
            uint32_t bf[4][4];
#pragma unroll
            for (int np = 0; np < 4; ++np)
                ldm_x4_trans(bf[np], bs + (ks * 16 + arow) * 272
                                        + (wn + np * 16 + acol) * 2);
#pragma unroll
            for (int mt = 0; mt < 2; ++mt)
#pragma unroll
                for (int nt = 0; nt < 8; ++nt)
                    mma16816(acc[mt][nt], af[mt], &bf[nt >> 1][(nt & 1) * 2]);
        }
    }

    // ------------------------------------------------------------------------
    // Epilogue: bias + activation, direct global stores
    // c-frag layout (m16n8): c0,c1 = (m=lane/4, n=(lane%4)*2+{0,1}); c2,c3 = m+8
    // ------------------------------------------------------------------------
#pragma unroll
    for (int mt = 0; mt < 2; ++mt) {
#pragma unroll
        for (int nt = 0; nt < 8; ++nt) {
            const int row = m0 + wm + mt * 16 + (lane >> 2);
            const int col = n0 + wn + nt * 8 + (lane & 3) * 2;
            const float2 bv = __ldg(reinterpret_cast<const float2*>(bias + col));
            float c0 = acc[mt][nt][0] + bv.x;
            float c1 = acc[mt][nt][1] + bv.y;
            float c2 = acc[mt][nt][2] + bv.x;
            float c3 = acc[mt][nt][3] + bv.y;
            if (EPI == 0) {
                c0 = fmaxf(c0, 0.0f); c1 = fmaxf(c1, 0.0f);
                c2 = fmaxf(c2, 0.0f); c3 = fmaxf(c3, 0.0f);
                __half2* Hp = reinterpret_cast<__half2*>(g_H);
                Hp[((size_t)row * N + col) >> 1]       = __floats2half2_rn(c0, c1);
                Hp[((size_t)(row + 8) * N + col) >> 1] = __floats2half2_rn(c2, c3);
            } else {
                float2 o0, o1;
                o0.x = 1.0f / (1.0f + __expf(-c0));
                o0.y = 1.0f / (1.0f + __expf(-c1));
                o1.x = 1.0f / (1.0f + __expf(-c2));
                o1.y = 1.0f / (1.0f + __expf(-c3));
                reinterpret_cast<float2*>(outF)[((size_t)row * N + col) >> 1]       = o0;
                reinterpret_cast<float2*>(outF)[((size_t)(row + 8) * N + col) >> 1] = o1;
            }
        }
    }
}

// ============================================================================
// Launch
// ============================================================================
extern "C" void kernel_launch(void* const* d_in, const int* in_sizes, int n_in,
                              void* d_out, int out_size)
{
    const float* x  = (const float*)d_in[0];
    const float* W1 = (const float*)d_in[1];
    const float* b1 = (const float*)d_in[2];
    const float* W2 = (const float*)d_in[3];
    const float* b2 = (const float*)d_in[4];
    float* out = (float*)d_out;

    constexpr int S = 4;
    constexpr size_t SMEM = S * (128 * 40 * 2) + S * (32 * 136 * 2);  // 75776 B
    cudaFuncSetAttribute(hgemm_kernel<0>, cudaFuncAttributeMaxDynamicSharedMemorySize, (int)SMEM);
    cudaFuncSetAttribute(hgemm_kernel<1>, cudaFuncAttributeMaxDynamicSharedMemorySize, (int)SMEM);

    // 1) fp32 -> fp16 conversions
    f2h_kernel<0><<<(BATCH * IN_F  / 4) / 256, 256>>>(x);   // g_X
    f2h_kernel<1><<<(IN_F  * HID_F / 4) / 256, 256>>>(W1);  // g_W1
    f2h_kernel<2><<<(HID_F * OUT_F / 4) / 256, 256>>>(W2);  // g_W2

    // 2) layer 1: H = relu(x@W1 + b1) -> fp16
    hgemm_kernel<0><<<dim3(BATCH / 128, HID_F / 128), 256, SMEM>>>(b1, nullptr);
    // 3) layer 2: out = sigmoid(H@W2 + b2) -> fp32
    hgemm_kernel<1><<<dim3(BATCH / 128, OUT_F / 128), 256, SMEM>>>(b2, out);
}

// round 14
// speedup vs baseline: 1.3076x; 1.3076x over previous
#include <cuda_runtime.h>
#include <cuda_fp16.h>
#include <cstdint>

// ============================================================================
// Problem constants
// ============================================================================
#define IN_F   2048
#define HID_F  8192
#define OUT_F  2048
#define BATCH  4096

// ============================================================================
// Scratch (device globals — allocation-free rule workaround)
// ============================================================================
__device__ __align__(16) __half g_X [(size_t)BATCH * IN_F];    // x  -> fp16
__device__ __align__(16) __half g_W1[(size_t)IN_F  * HID_F];   // W1 -> fp16 ([K,N] layout)
__device__ __align__(16) __half g_W2[(size_t)HID_F * OUT_F];   // W2 -> fp16
__device__ __align__(16) __half g_H [(size_t)BATCH * HID_F];   // relu(x@W1+b1) fp16

// ============================================================================
// Helpers (sm_80-baseline PTX only — legal under compute_103 target)
// ============================================================================
__device__ __forceinline__ uint32_t smem_to_u32(const void* smem_ptr) {
    uint32_t addr;
    asm("{ .reg .u64 tmp; cvta.to.shared.u64 tmp, %1; cvt.u32.u64 %0, tmp; }"
        : "=r"(addr) : "l"(smem_ptr));
    return addr;
}

__device__ __forceinline__ void cp_async16(uint32_t dst, const void* src) {
    asm volatile("cp.async.cg.shared.global [%0], [%1], 16;" :: "r"(dst), "l"(src));
}
__device__ __forceinline__ void cp_commit() {
    asm volatile("cp.async.commit_group;" ::: "memory");
}

__device__ __forceinline__ void ldm_x4(uint32_t* r, uint32_t addr) {
    asm volatile("ldmatrix.sync.aligned.m8n8.x4.shared.b16 {%0,%1,%2,%3}, [%4];"
                 : "=r"(r[0]), "=r"(r[1]), "=r"(r[2]), "=r"(r[3]) : "r"(addr));
}
__device__ __forceinline__ void ldm_x4_trans(uint32_t* r, uint32_t addr) {
    asm volatile("ldmatrix.sync.aligned.m8n8.x4.trans.shared.b16 {%0,%1,%2,%3}, [%4];"
                 : "=r"(r[0]), "=r"(r[1]), "=r"(r[2]), "=r"(r[3]) : "r"(addr));
}

__device__ __forceinline__ void mma16816(float* d, const uint32_t* a, const uint32_t* b) {
    asm volatile(
        "mma.sync.aligned.m16n8k16.row.col.f32.f16.f16.f32 "
        "{%0,%1,%2,%3}, {%4,%5,%6,%7}, {%8,%9}, {%0,%1,%2,%3};"
        : "+f"(d[0]), "+f"(d[1]), "+f"(d[2]), "+f"(d[3])
        : "r"(a[0]), "r"(a[1]), "r"(a[2]), "r"(a[3]), "r"(b[0]), "r"(b[1]));
}

// ============================================================================
// fp32 -> fp16 conversion (4 elems / thread)
// ============================================================================
template<int SEL>
__global__ void __launch_bounds__(256) f2h_kernel(const float* __restrict__ src) {
    __half* dst = (SEL == 0) ? g_X : (SEL == 1) ? g_W1 : g_W2;
    size_t i = (size_t)blockIdx.x * blockDim.x + threadIdx.x;
    float4 v = reinterpret_cast<const float4*>(src)[i];
    __half2 h0 = __floats2half2_rn(v.x, v.y);
    __half2 h1 = __floats2half2_rn(v.z, v.w);
    reinterpret_cast<__half2*>(dst)[2 * i]     = h0;
    reinterpret_cast<__half2*>(dst)[2 * i + 1] = h1;
}

// ============================================================================
// fp16 GEMM, fp32 accumulate:  C[M,N] = A[M,K] @ B[K,N]  (+bias, activation)
//   EPI==0: A=g_X,  B=g_W1, relu    -> g_H (fp16)      [M=4096,K=2048,N=8192]
//   EPI==1: A=g_H,  B=g_W2, sigmoid -> outF (fp32)     [M=4096,K=8192,N=2048]
//
// CTA tile 128x128, BK=32, 4-stage cp.async pipeline, 128 threads = 4 warps
// in a 2(m) x 2(n) grid, warp tile 64x64 (8 LDSM : 32 MMA per k16 step).
// __launch_bounds__(128, 2) -> 2 CTAs/SM (8 warps) for barrier/epilogue overlap.
// Padded smem rows (verified conflict-free):
//   A stage: [128][40] fp16 (row 80B,  bank seq {0,20,8,28,16,4,24,12})
//   B stage: [32][136] fp16 (row 272B, bank seq {0,4,8,...,28})
// ============================================================================
template<int EPI>
__global__ void __launch_bounds__(128, 2)
hgemm_kernel(const float* __restrict__ bias, float* __restrict__ outF)
{
    constexpr int K  = (EPI == 0) ? IN_F  : HID_F;
    constexpr int N  = (EPI == 0) ? HID_F : OUT_F;
    constexpr int BM = 128, BN = 128, BK = 32, S = 4;
    constexpr int KT = K / BK;
    constexpr int A_STG = BM * 40 * 2;    // 10240 B
    constexpr int B_STG = BK * 136 * 2;   //  8704 B

    const __half* A = (EPI == 0) ? g_X  : g_H;
    const __half* B = (EPI == 0) ? g_W1 : g_W2;

    extern __shared__ char smem[];
    const uint32_t sA = smem_to_u32(smem);
    const uint32_t sB = sA + S * A_STG;

    const int tid  = threadIdx.x;
    const int lane = tid & 31;
    const int wid  = tid >> 5;             // 4 warps
    const int wm   = (wid & 1) << 6;       // warp m offset: 0, 64
    const int wn   = (wid >> 1) << 6;      // warp n offset: 0, 64
    const int m0   = blockIdx.x * BM;
    const int n0   = blockIdx.y * BN;

    auto load_stage = [&](int kt, int s) {
        const int k0 = kt * BK;
        const uint32_t as = sA + s * A_STG;
        // A tile: 128 rows x 32 halves = 512 x 16B chunks (4 chunks/row)
#pragma unroll
        for (int it = 0; it < 4; ++it) {
            int g = tid + it * 128;
            int r = g >> 2, c = g & 3;
            cp_async16(as + r * 80 + c * 16,
                       A + (size_t)(m0 + r) * K + k0 + c * 8);
        }
        const uint32_t bs = sB + s * B_STG;
        // B tile: 32 rows x 128 halves = 512 x 16B chunks (16 chunks/row)
#pragma unroll
        for (int it = 0; it < 4; ++it) {
            int g = tid + it * 128;
            int r = g >> 4, c = g & 15;
            cp_async16(bs + r * 272 + c * 16,
                       B + (size_t)(k0 + r) * N + n0 + c * 8);
        }
        cp_commit();
    };

    float acc[4][8][4];
#pragma unroll
    for (int mt = 0; mt < 4; ++mt)
#pragma unroll
        for (int nt = 0; nt < 8; ++nt)
#pragma unroll
            for (int q = 0; q < 4; ++q) acc[mt][nt][q] = 0.0f;

    // prologue: fill S-1 stages
#pragma unroll
    for (int st = 0; st < S - 1; ++st) load_stage(st, st);

    const int arow = lane & 15;            // ldmatrix row-within-16
    const int acol = (lane >> 4) << 3;     // 0 or 8 (col half)

    for (int kt = 0; kt < KT; ++kt) {
        if (kt < KT - (S - 1)) asm volatile("cp.async.wait_group %0;" :: "n"(S - 2) : "memory");
        else                   asm volatile("cp.async.wait_group 0;" ::: "memory");
        __syncthreads();

        if (kt + S - 1 < KT) load_stage(kt + S - 1, (kt + S - 1) % S);

        const uint32_t as = sA + (kt % S) * A_STG;
        const uint32_t bs = sB + (kt % S) * B_STG;
#pragma unroll
        for (int ks = 0; ks < 2; ++ks) {
            uint32_t af[4][4];
#pragma unroll
            for (int mt = 0; mt < 4; ++mt)
                ldm_x4(af[mt], as + (wm + mt * 16 + arow) * 80 + (ks * 16 + acol) * 2);
            uint32_t bf[4][4];
#pragma unroll
            for (int np = 0; np < 4; ++np)
                ldm_x4_trans(bf[np], bs + (ks * 16 + arow) * 272
                                        + (wn + np * 16 + acol) * 2);
#pragma unroll
            for (int mt = 0; mt < 4; ++mt)
#pragma unroll
                for (int nt = 0; nt < 8; ++nt)
                    mma16816(acc[mt][nt], af[mt], &bf[nt >> 1][(nt & 1) * 2]);
        }
    }

    // ------------------------------------------------------------------------
    // Epilogue: bias + activation, direct global stores
    // c-frag layout (m16n8): c0,c1 = (m=lane/4, n=(lane%4)*2+{0,1}); c2,c3 = m+8
    // ------------------------------------------------------------------------
#pragma unroll
    for (int mt = 0; mt < 4; ++mt) {
#pragma unroll
        for (int nt = 0; nt < 8; ++nt) {
            const int row = m0 + wm + mt * 16 + (lane >> 2);
            const int col = n0 + wn + nt * 8 + (lane & 3) * 2;
            const float2 bv = __ldg(reinterpret_cast<const float2*>(bias + col));
            float c0 = acc[mt][nt][0] + bv.x;
            float c1 = acc[mt][nt][1] + bv.y;
            float c2 = acc[mt][nt][2] + bv.x;
            float c3 = acc[mt][nt][3] + bv.y;
            if (EPI == 0) {
                c0 = fmaxf(c0, 0.0f); c1 = fmaxf(c1, 0.0f);
                c2 = fmaxf(c2, 0.0f); c3 = fmaxf(c3, 0.0f);
                __half2* Hp = reinterpret_cast<__half2*>(g_H);
                Hp[((size_t)row * N + col) >> 1]       = __floats2half2_rn(c0, c1);
                Hp[((size_t)(row + 8) * N + col) >> 1] = __floats2half2_rn(c2, c3);
            } else {
                float2 o0, o1;
                o0.x = 1.0f / (1.0f + __expf(-c0));
                o0.y = 1.0f / (1.0f + __expf(-c1));
                o1.x = 1.0f / (1.0f + __expf(-c2));
                o1.y = 1.0f / (1.0f + __expf(-c3));
                reinterpret_cast<float2*>(outF)[((size_t)row * N + col) >> 1]       = o0;
                reinterpret_cast<float2*>(outF)[((size_t)(row + 8) * N + col) >> 1] = o1;
            }
        }
    }
}

// ============================================================================
// Launch
// ============================================================================
extern "C" void kernel_launch(void* const* d_in, const int* in_sizes, int n_in,
                              void* d_out, int out_size)
{
    const float* x  = (const float*)d_in[0];
    const float* W1 = (const float*)d_in[1];
    const float* b1 = (const float*)d_in[2];
    const float* W2 = (const float*)d_in[3];
    const float* b2 = (const float*)d_in[4];
    float* out = (float*)d_out;

    constexpr int S = 4;
    constexpr size_t SMEM = S * (128 * 40 * 2) + S * (32 * 136 * 2);  // 75776 B
    cudaFuncSetAttribute(hgemm_kernel<0>, cudaFuncAttributeMaxDynamicSharedMemorySize, (int)SMEM);
    cudaFuncSetAttribute(hgemm_kernel<1>, cudaFuncAttributeMaxDynamicSharedMemorySize, (int)SMEM);

    // 1) fp32 -> fp16 conversions
    f2h_kernel<0><<<(BATCH * IN_F  / 4) / 256, 256>>>(x);   // g_X
    f2h_kernel<1><<<(IN_F  * HID_F / 4) / 256, 256>>>(W1);  // g_W1
    f2h_kernel<2><<<(HID_F * OUT_F / 4) / 256, 256>>>(W2);  // g_W2

    // 2) layer 1: H = relu(x@W1 + b1) -> fp16
    hgemm_kernel<0><<<dim3(BATCH / 128, HID_F / 128), 128, SMEM>>>(b1, nullptr);
    // 3) layer 2: out = sigmoid(H@W2 + b2) -> fp32
    hgemm_kernel<1><<<dim3(BATCH / 128, OUT_F / 128), 128, SMEM>>>(b2, out);
}

// round 15
// speedup vs baseline: 1.3509x; 1.0331x over previous
#include <cuda_runtime.h>
#include <cuda_fp16.h>
#include <cstdint>

// ============================================================================
// Problem constants
// ============================================================================
#define IN_F   2048
#define HID_F  8192
#define OUT_F  2048
#define BATCH  4096

// ============================================================================
// Scratch (device globals — allocation-free rule workaround)
// ============================================================================
__device__ __align__(16) __half g_X [(size_t)BATCH * IN_F];    // x  -> fp16
__device__ __align__(16) __half g_W1[(size_t)IN_F  * HID_F];   // W1 -> fp16 ([K,N] layout)
__device__ __align__(16) __half g_W2[(size_t)HID_F * OUT_F];   // W2 -> fp16
__device__ __align__(16) __half g_H [(size_t)BATCH * HID_F];   // relu(x@W1+b1) fp16

// ============================================================================
// Helpers (sm_80-baseline PTX only — legal under compute_103 target)
// ============================================================================
__device__ __forceinline__ uint32_t smem_to_u32(const void* smem_ptr) {
    uint32_t addr;
    asm("{ .reg .u64 tmp; cvta.to.shared.u64 tmp, %1; cvt.u32.u64 %0, tmp; }"
        : "=r"(addr) : "l"(smem_ptr));
    return addr;
}

__device__ __forceinline__ void cp_async16(uint32_t dst, const void* src) {
    asm volatile("cp.async.cg.shared.global [%0], [%1], 16;" :: "r"(dst), "l"(src));
}
__device__ __forceinline__ void cp_commit() {
    asm volatile("cp.async.commit_group;" ::: "memory");
}

__device__ __forceinline__ void ldm_x4(uint32_t* r, uint32_t addr) {
    asm volatile("ldmatrix.sync.aligned.m8n8.x4.shared.b16 {%0,%1,%2,%3}, [%4];"
                 : "=r"(r[0]), "=r"(r[1]), "=r"(r[2]), "=r"(r[3]) : "r"(addr));
}
__device__ __forceinline__ void ldm_x4_trans(uint32_t* r, uint32_t addr) {
    asm volatile("ldmatrix.sync.aligned.m8n8.x4.trans.shared.b16 {%0,%1,%2,%3}, [%4];"
                 : "=r"(r[0]), "=r"(r[1]), "=r"(r[2]), "=r"(r[3]) : "r"(addr));
}

__device__ __forceinline__ void mma16816(float* d, const uint32_t* a, const uint32_t* b) {
    asm volatile(
        "mma.sync.aligned.m16n8k16.row.col.f32.f16.f16.f32 "
        "{%0,%1,%2,%3}, {%4,%5,%6,%7}, {%8,%9}, {%0,%1,%2,%3};"
        : "+f"(d[0]), "+f"(d[1]), "+f"(d[2]), "+f"(d[3])
        : "r"(a[0]), "r"(a[1]), "r"(a[2]), "r"(a[3]), "r"(b[0]), "r"(b[1]));
}

// ============================================================================
// fp32 -> fp16 conversion (4 elems / thread)
// ============================================================================
template<int SEL>
__global__ void __launch_bounds__(256) f2h_kernel(const float* __restrict__ src) {
    __half* dst = (SEL == 0) ? g_X : (SEL == 1) ? g_W1 : g_W2;
    size_t i = (size_t)blockIdx.x * blockDim.x + threadIdx.x;
    float4 v = reinterpret_cast<const float4*>(src)[i];
    __half2 h0 = __floats2half2_rn(v.x, v.y);
    __half2 h1 = __floats2half2_rn(v.z, v.w);
    reinterpret_cast<__half2*>(dst)[2 * i]     = h0;
    reinterpret_cast<__half2*>(dst)[2 * i + 1] = h1;
}

// ============================================================================
// fp16 GEMM, fp32 accumulate:  C[M,N] = A[M,K] @ B[K,N]  (+bias, activation)
//   EPI==0: A=g_X,  B=g_W1, relu    -> g_H (fp16)      [M=4096,K=2048,N=8192]
//   EPI==1: A=g_H,  B=g_W2, sigmoid -> outF (fp32)     [M=4096,K=8192,N=2048]
//
// CTA tile 128x128, BK=32, 4-stage cp.async pipeline, 128 threads = 4 warps
// in a 2(m) x 2(n) grid, warp tile 64x64. Register-level fragment double
// buffering: LDSM batch for ks=1 issues before the ks=0 MMA block so the
// ~230 cyc of MMA work hides the second batch's shared-memory latency.
// __launch_bounds__(128, 2) -> 2 CTAs/SM for barrier/epilogue overlap.
// Padded smem rows (verified conflict-free):
//   A stage: [128][40] fp16 (row 80B,  bank seq {0,20,8,28,16,4,24,12})
//   B stage: [32][136] fp16 (row 272B, bank seq {0,4,8,...,28})
// ============================================================================
template<int EPI>
__global__ void __launch_bounds__(128, 2)
hgemm_kernel(const float* __restrict__ bias, float* __restrict__ outF)
{
    constexpr int K  = (EPI == 0) ? IN_F  : HID_F;
    constexpr int N  = (EPI == 0) ? HID_F : OUT_F;
    constexpr int BM = 128, BN = 128, BK = 32, S = 4;
    constexpr int KT = K / BK;
    constexpr int A_STG = BM * 40 * 2;    // 10240 B
    constexpr int B_STG = BK * 136 * 2;   //  8704 B

    const __half* A = (EPI == 0) ? g_X  : g_H;
    const __half* B = (EPI == 0) ? g_W1 : g_W2;

    extern __shared__ char smem[];
    const uint32_t sA = smem_to_u32(smem);
    const uint32_t sB = sA + S * A_STG;

    const int tid  = threadIdx.x;
    const int lane = tid & 31;
    const int wid  = tid >> 5;             // 4 warps
    const int wm   = (wid & 1) << 6;       // warp m offset: 0, 64
    const int wn   = (wid >> 1) << 6;      // warp n offset: 0, 64
    const int m0   = blockIdx.x * BM;
    const int n0   = blockIdx.y * BN;

    auto load_stage = [&](int kt, int s) {
        const int k0 = kt * BK;
        const uint32_t as = sA + s * A_STG;
        // A tile: 128 rows x 32 halves = 512 x 16B chunks (4 chunks/row)
#pragma unroll
        for (int it = 0; it < 4; ++it) {
            int g = tid + it * 128;
            int r = g >> 2, c = g & 3;
            cp_async16(as + r * 80 + c * 16,
                       A + (size_t)(m0 + r) * K + k0 + c * 8);
        }
        const uint32_t bs = sB + s * B_STG;
        // B tile: 32 rows x 128 halves = 512 x 16B chunks (16 chunks/row)
#pragma unroll
        for (int it = 0; it < 4; ++it) {
            int g = tid + it * 128;
            int r = g >> 4, c = g & 15;
            cp_async16(bs + r * 272 + c * 16,
                       B + (size_t)(k0 + r) * N + n0 + c * 8);
        }
        cp_commit();
    };

    float acc[4][8][4];
#pragma unroll
    for (int mt = 0; mt < 4; ++mt)
#pragma unroll
        for (int nt = 0; nt < 8; ++nt)
#pragma unroll
            for (int q = 0; q < 4; ++q) acc[mt][nt][q] = 0.0f;

    // prologue: fill S-1 stages
#pragma unroll
    for (int st = 0; st < S - 1; ++st) load_stage(st, st);

    const int arow = lane & 15;            // ldmatrix row-within-16
    const int acol = (lane >> 4) << 3;     // 0 or 8 (col half)

    // double-buffered fragments
    uint32_t af[2][4][4], bf[2][4][4];

    auto ldm_frags = [&](int buf, uint32_t as, uint32_t bs, int ks) {
#pragma unroll
        for (int mt = 0; mt < 4; ++mt)
            ldm_x4(af[buf][mt], as + (wm + mt * 16 + arow) * 80 + (ks * 16 + acol) * 2);
#pragma unroll
        for (int np = 0; np < 4; ++np)
            ldm_x4_trans(bf[buf][np], bs + (ks * 16 + arow) * 272
                                         + (wn + np * 16 + acol) * 2);
    };
    auto mma_block = [&](int buf) {
#pragma unroll
        for (int mt = 0; mt < 4; ++mt)
#pragma unroll
            for (int nt = 0; nt < 8; ++nt)
                mma16816(acc[mt][nt], af[buf][mt], &bf[buf][nt >> 1][(nt & 1) * 2]);
    };

    for (int kt = 0; kt < KT; ++kt) {
        if (kt < KT - (S - 1)) asm volatile("cp.async.wait_group %0;" :: "n"(S - 2) : "memory");
        else                   asm volatile("cp.async.wait_group 0;" ::: "memory");
        __syncthreads();

        const uint32_t as = sA + (kt % S) * A_STG;
        const uint32_t bs = sB + (kt % S) * B_STG;

        // issue order: LDSM(ks=0) -> stage-fill cp.async (hides LDSM latency)
        //              -> LDSM(ks=1) -> MMA(ks=0) -> MMA(ks=1)
        ldm_frags(0, as, bs, 0);
        if (kt + S - 1 < KT) load_stage(kt + S - 1, (kt + S - 1) % S);
        ldm_frags(1, as, bs, 1);
        mma_block(0);
        mma_block(1);
    }

    // ------------------------------------------------------------------------
    // Epilogue: bias + activation, direct global stores
    // c-frag layout (m16n8): c0,c1 = (m=lane/4, n=(lane%4)*2+{0,1}); c2,c3 = m+8
    // ------------------------------------------------------------------------
#pragma unroll
    for (int mt = 0; mt < 4; ++mt) {
#pragma unroll
        for (int nt = 0; nt < 8; ++nt) {
            const int row = m0 + wm + mt * 16 + (lane >> 2);
            const int col = n0 + wn + nt * 8 + (lane & 3) * 2;
            const float2 bv = __ldg(reinterpret_cast<const float2*>(bias + col));
            float c0 = acc[mt][nt][0] + bv.x;
            float c1 = acc[mt][nt][1] + bv.y;
            float c2 = acc[mt][nt][2] + bv.x;
            float c3 = acc[mt][nt][3] + bv.y;
            if (EPI == 0) {
                c0 = fmaxf(c0, 0.0f); c1 = fmaxf(c1, 0.0f);
                c2 = fmaxf(c2, 0.0f); c3 = fmaxf(c3, 0.0f);
                __half2* Hp = reinterpret_cast<__half2*>(g_H);
                Hp[((size_t)row * N + col) >> 1]       = __floats2half2_rn(c0, c1);
                Hp[((size_t)(row + 8) * N + col) >> 1] = __floats2half2_rn(c2, c3);
            } else {
                float2 o0, o1;
                o0.x = 1.0f / (1.0f + __expf(-c0));
                o0.y = 1.0f / (1.0f + __expf(-c1));
                o1.x = 1.0f / (1.0f + __expf(-c2));
                o1.y = 1.0f / (1.0f + __expf(-c3));
                reinterpret_cast<float2*>(outF)[((size_t)row * N + col) >> 1]       = o0;
                reinterpret_cast<float2*>(outF)[((size_t)(row + 8) * N + col) >> 1] = o1;
            }
        }
    }
}

// ============================================================================
// Launch
// ============================================================================
extern "C" void kernel_launch(void* const* d_in, const int* in_sizes, int n_in,
                              void* d_out, int out_size)
{
    const float* x  = (const float*)d_in[0];
    const float* W1 = (const float*)d_in[1];
    const float* b1 = (const float*)d_in[2];
    const float* W2 = (const float*)d_in[3];
    const float* b2 = (const float*)d_in[4];
    float* out = (float*)d_out;

    constexpr int S = 4;
    constexpr size_t SMEM = S * (128 * 40 * 2) + S * (32 * 136 * 2);  // 75776 B
    cudaFuncSetAttribute(hgemm_kernel<0>, cudaFuncAttributeMaxDynamicSharedMemorySize, (int)SMEM);
    cudaFuncSetAttribute(hgemm_kernel<1>, cudaFuncAttributeMaxDynamicSharedMemorySize, (int)SMEM);

    // 1) fp32 -> fp16 conversions
    f2h_kernel<0><<<(BATCH * IN_F  / 4) / 256, 256>>>(x);   // g_X
    f2h_kernel<1><<<(IN_F  * HID_F / 4) / 256, 256>>>(W1);  // g_W1
    f2h_kernel<2><<<(HID_F * OUT_F / 4) / 256, 256>>>(W2);  // g_W2

    // 2) layer 1: H = relu(x@W1 + b1) -> fp16
    hgemm_kernel<0><<<dim3(BATCH / 128, HID_F / 128), 128, SMEM>>>(b1, nullptr);
    // 3) layer 2: out = sigmoid(H@W2 + b2) -> fp32
    hgemm_kernel<1><<<dim3(BATCH / 128, OUT_F / 128), 128, SMEM>>>(b2, out);
}